// round 2
// baseline (speedup 1.0000x reference)
#include <cuda_runtime.h>
#include <math.h>

#define DT 0.1f
#define EPS_STAT 0.01f
#define EPB 4  // batch elements per thread

template <int BLOCK>
__global__ void __launch_bounds__(BLOCK)
kalman_fused_kernel(const float* __restrict__ in, float* __restrict__ out,
                    const float* __restrict__ sa_p, const float* __restrict__ so_p,
                    const float* __restrict__ si_p,
                    int B, int n_est, int n_pred) {
    const int i = blockIdx.x * BLOCK + threadIdx.x;       // group index
    const int b0 = i * EPB;                               // first batch elem
    if (b0 >= B) return;
    // B is a multiple of EPB in this problem (131072); guard defensively anyway.
    const bool full = (b0 + EPB <= B);

    // ---- covariance recursion constants (uniform; computed per-thread, cheap) ----
    const float sa = __ldg(sa_p), so = __ldg(so_p), si = __ldg(si_p);
    const float g0  = DT * DT * 0.5f;
    const float q00 = sa * sa * (g0 * g0);
    const float q01 = sa * sa * (g0 * DT);
    const float q11 = sa * sa * (DT * DT);
    const float r   = so * so;
    const float eps2 = EPS_STAT * EPS_STAT;
    float P00 = si * si, P01 = 0.0f, P11 = si * si;

    // ---- load first two measurement rows (4 elems = 8 floats = 2 float4) ----
    const float4* __restrict__ in4 = reinterpret_cast<const float4*>(in);
    const int rowF4 = B / 2;  // float4s per timestep row (B*2 floats / 4)

    float4 a0, a1, c0, c1;
    if (full) {
        a0 = in4[2 * i];            a1 = in4[2 * i + 1];
        c0 = in4[rowF4 + 2 * i];    c1 = in4[rowF4 + 2 * i + 1];
    } else {
        a0 = a1 = c0 = c1 = make_float4(0.f, 0.f, 0.f, 0.f);
    }

    float px[EPB], py[EPB], vx[EPB], vy[EPB];
    px[0]=a0.x; py[0]=a0.y; px[1]=a0.z; py[1]=a0.w;
    px[2]=a1.x; py[2]=a1.y; px[3]=a1.z; py[3]=a1.w;
    float zx[EPB], zy[EPB];
    zx[0]=c0.x; zy[0]=c0.y; zx[1]=c0.z; zy[1]=c0.w;
    zx[2]=c1.x; zy[2]=c1.y; zx[3]=c1.z; zy[3]=c1.w;
    #pragma unroll
    for (int e = 0; e < EPB; e++) {
        vx[e] = (zx[e] - px[e]) * (1.0f / DT);
        vy[e] = (zy[e] - py[e]) * (1.0f / DT);
    }

    float4* __restrict__ out4 = reinterpret_cast<float4*>(out);
    const long long rowF4o = (long long)B * 5 / 4;  // float4s per output timestep
    long long wbase = (long long)i * 5;             // 20 floats = 5 float4 per group

    // ---------------- estimation phase ----------------
    for (int k = 0; k < n_est; k++) {
        // covariance predict (2x2, per-axis, uniform)
        float nP00 = P00 + 2.0f * DT * P01 + DT * DT * P11 + q00;
        float nP01 = P01 + DT * P11 + q01;
        float nP11 = P11 + q11;
        P00 = nP00; P01 = nP01; P11 = nP11;
        float S  = P00 + r;
        float rs = __frcp_rn(S);
        float K0 = P00 * rs;
        float K1 = P01 * rs;

        // mean predict + update (data-dependent)
        #pragma unroll
        for (int e = 0; e < EPB; e++) {
            px[e] += DT * vx[e];
            py[e] += DT * vy[e];
            float yx = zx[e] - px[e];
            float yy = zy[e] - py[e];
            px[e] += K0 * yx; vx[e] += K1 * yx;
            py[e] += K0 * yy; vy[e] += K1 * yy;
        }

        // prefetch next measurement row
        if (k + 1 < n_est && full) {
            const float4* src = in4 + (size_t)(k + 2) * rowF4 + 2 * i;
            float4 n0 = src[0], n1 = src[1];
            zx[0]=n0.x; zy[0]=n0.y; zx[1]=n0.z; zy[1]=n0.w;
            zx[2]=n1.x; zy[2]=n1.y; zx[3]=n1.z; zy[3]=n1.w;
        }

        // covariance update (Joseph, uniform)
        float omk = 1.0f - K0;
        float A00 = omk * P00;
        float A01 = omk * P01;
        float A10 = P01 - K1 * P00;
        float A11 = P11 - K1 * P01;
        P00 =  A00 * omk      + r * K0 * K0;
        P01 = -A00 * K1 + A01 + r * K0 * K1;
        P11 = -A10 * K1 + A11 + r * K1 * K1;

        float s = sqrtf(fmaxf(P00, eps2));

        if (full) {
            float4* d = out4 + (long long)k * rowF4o + wbase;
            d[0] = make_float4(px[0], py[0], s, s);
            d[1] = make_float4(0.f,  px[1], py[1], s);
            d[2] = make_float4(s,    0.f,  px[2], py[2]);
            d[3] = make_float4(s,    s,    0.f,  px[3]);
            d[4] = make_float4(py[3], s,   s,    0.f);
        } else {
            float* d = out + (long long)k * B * 5 + (long long)b0 * 5;
            for (int e = 0; e < EPB && b0 + e < B; e++) {
                d[5*e+0]=px[e]; d[5*e+1]=py[e]; d[5*e+2]=s; d[5*e+3]=s; d[5*e+4]=0.f;
            }
        }
    }

    // ---------------- prediction phase ----------------
    for (int j = 0; j < n_pred; j++) {
        float nP00 = P00 + 2.0f * DT * P01 + DT * DT * P11 + q00;
        float nP01 = P01 + DT * P11 + q01;
        float nP11 = P11 + q11;
        P00 = nP00; P01 = nP01; P11 = nP11;
        float s = sqrtf(fmaxf(P00, eps2));

        #pragma unroll
        for (int e = 0; e < EPB; e++) {
            px[e] += DT * vx[e];
            py[e] += DT * vy[e];
        }

        const long long t = n_est + j;
        if (full) {
            float4* d = out4 + t * rowF4o + wbase;
            d[0] = make_float4(px[0], py[0], s, s);
            d[1] = make_float4(0.f,  px[1], py[1], s);
            d[2] = make_float4(s,    0.f,  px[2], py[2]);
            d[3] = make_float4(s,    s,    0.f,  px[3]);
            d[4] = make_float4(py[3], s,   s,    0.f);
        } else {
            float* d = out + t * B * 5 + (long long)b0 * 5;
            for (int e = 0; e < EPB && b0 + e < B; e++) {
                d[5*e+0]=px[e]; d[5*e+1]=py[e]; d[5*e+2]=s; d[5*e+3]=s; d[5*e+4]=0.f;
            }
        }
    }
}

extern "C" void kernel_launch(void* const* d_in, const int* in_sizes, int n_in,
                              void* d_out, int out_size) {
    const float* inputs  = (const float*)d_in[0];
    const float* sigma_a = (const float*)d_in[1];
    const float* sigma_o = (const float*)d_in[2];
    const float* sigma_i = (const float*)d_in[3];

    const int T_OBS = 10;
    const int B = in_sizes[0] / (T_OBS * 2);
    const int n_est = T_OBS - 1;                // 9
    const int totalSteps = out_size / (B * 5);  // 39
    const int n_pred = totalSteps - n_est;      // 30

    constexpr int BLOCK = 128;
    const int groups = (B + EPB - 1) / EPB;
    const int grid = (groups + BLOCK - 1) / BLOCK;
    kalman_fused_kernel<BLOCK><<<grid, BLOCK>>>(inputs, (float*)d_out,
                                                sigma_a, sigma_o, sigma_i,
                                                B, n_est, n_pred);
}

// round 3
// speedup vs baseline: 1.0008x; 1.0008x over previous
#include <cuda_runtime.h>
#include <math.h>

#define DT 0.1f
#define EPS_STAT 0.01f
#define EPB 4      // batch elements per thread
#define TCHUNKS 4  // time chunks (redundant est recursion, partitioned stores)

template <int BLOCK>
__global__ void __launch_bounds__(BLOCK)
kalman_fused_kernel(const float* __restrict__ in, float* __restrict__ out,
                    const float* __restrict__ sa_p, const float* __restrict__ so_p,
                    const float* __restrict__ si_p,
                    int B, int n_est, int n_pred) {
    const int chunk = blockIdx.y;
    const int total = n_est + n_pred;
    const int lo = (chunk * total) / TCHUNKS;        // first row this thread stores
    const int hi = ((chunk + 1) * total) / TCHUNKS;  // one past last

    const int i = blockIdx.x * BLOCK + threadIdx.x;  // batch-group index
    const int b0 = i * EPB;
    if (b0 >= B) return;
    const bool full = (b0 + EPB <= B);

    // ---- uniform covariance-recursion constants ----
    const float sa = __ldg(sa_p), so = __ldg(so_p), si = __ldg(si_p);
    const float g0  = DT * DT * 0.5f;
    const float q00 = sa * sa * (g0 * g0);
    const float q01 = sa * sa * (g0 * DT);
    const float q11 = sa * sa * (DT * DT);
    const float r   = so * so;
    const float eps2 = EPS_STAT * EPS_STAT;
    float P00 = si * si, P01 = 0.0f, P11 = si * si;

    // ---- load rows 0 and 1 ----
    const float4* __restrict__ in4 = reinterpret_cast<const float4*>(in);
    const int rowF4 = B / 2;

    float4 a0, a1, c0, c1;
    if (full) {
        a0 = in4[2 * i];         a1 = in4[2 * i + 1];
        c0 = in4[rowF4 + 2 * i]; c1 = in4[rowF4 + 2 * i + 1];
    } else {
        a0 = a1 = c0 = c1 = make_float4(0.f, 0.f, 0.f, 0.f);
    }

    float px[EPB], py[EPB], vx[EPB], vy[EPB], zx[EPB], zy[EPB];
    px[0]=a0.x; py[0]=a0.y; px[1]=a0.z; py[1]=a0.w;
    px[2]=a1.x; py[2]=a1.y; px[3]=a1.z; py[3]=a1.w;
    zx[0]=c0.x; zy[0]=c0.y; zx[1]=c0.z; zy[1]=c0.w;
    zx[2]=c1.x; zy[2]=c1.y; zx[3]=c1.z; zy[3]=c1.w;
    #pragma unroll
    for (int e = 0; e < EPB; e++) {
        vx[e] = (zx[e] - px[e]) * (1.0f / DT);
        vy[e] = (zy[e] - py[e]) * (1.0f / DT);
    }

    float4* __restrict__ out4 = reinterpret_cast<float4*>(out);
    const long long rowF4o = (long long)B * 5 / 4;
    const long long wbase = (long long)i * 5;

    // ---------------- estimation phase (all chunks run it; chunk-owned rows stored) ----------------
    for (int k = 0; k < n_est; k++) {
        float nP00 = P00 + 2.0f * DT * P01 + DT * DT * P11 + q00;
        float nP01 = P01 + DT * P11 + q01;
        float nP11 = P11 + q11;
        P00 = nP00; P01 = nP01; P11 = nP11;
        float S  = P00 + r;
        float rs = __frcp_rn(S);
        float K0 = P00 * rs;
        float K1 = P01 * rs;

        #pragma unroll
        for (int e = 0; e < EPB; e++) {
            px[e] += DT * vx[e];
            py[e] += DT * vy[e];
            float yx = zx[e] - px[e];
            float yy = zy[e] - py[e];
            px[e] += K0 * yx; vx[e] += K1 * yx;
            py[e] += K0 * yy; vy[e] += K1 * yy;
        }

        if (k + 1 < n_est && full) {
            const float4* src = in4 + (size_t)(k + 2) * rowF4 + 2 * i;
            float4 n0 = src[0], n1 = src[1];
            zx[0]=n0.x; zy[0]=n0.y; zx[1]=n0.z; zy[1]=n0.w;
            zx[2]=n1.x; zy[2]=n1.y; zx[3]=n1.z; zy[3]=n1.w;
        }

        float omk = 1.0f - K0;
        float A00 = omk * P00;
        float A01 = omk * P01;
        float A10 = P01 - K1 * P00;
        float A11 = P11 - K1 * P01;
        P00 =  A00 * omk      + r * K0 * K0;
        P01 = -A00 * K1 + A01 + r * K0 * K1;
        P11 = -A10 * K1 + A11 + r * K1 * K1;

        if (k >= lo && k < hi) {
            float s = sqrtf(fmaxf(P00, eps2));
            if (full) {
                float4* d = out4 + (long long)k * rowF4o + wbase;
                d[0] = make_float4(px[0], py[0], s, s);
                d[1] = make_float4(0.f,  px[1], py[1], s);
                d[2] = make_float4(s,    0.f,  px[2], py[2]);
                d[3] = make_float4(s,    s,    0.f,  px[3]);
                d[4] = make_float4(py[3], s,   s,    0.f);
            } else {
                float* d = out + (long long)k * B * 5 + (long long)b0 * 5;
                for (int e = 0; e < EPB && b0 + e < B; e++) {
                    d[5*e+0]=px[e]; d[5*e+1]=py[e]; d[5*e+2]=s; d[5*e+3]=s; d[5*e+4]=0.f;
                }
            }
        }
    }

    // ---------------- prediction phase (closed-form positions; uniform P recursion) ----------------
    if (hi <= n_est) return;  // chunk 0 owns only est rows

    const int jp_hi = hi - n_est;          // exclusive local pred bound
    const int jp_lo = max(lo - n_est, 0);  // inclusive
    for (int jp = 0; jp < jp_hi; jp++) {
        float nP00 = P00 + 2.0f * DT * P01 + DT * DT * P11 + q00;
        float nP01 = P01 + DT * P11 + q01;
        float nP11 = P11 + q11;
        P00 = nP00; P01 = nP01; P11 = nP11;

        if (jp >= jp_lo) {
            float s = sqrtf(fmaxf(P00, eps2));
            float tt = (float)(jp + 1) * DT;
            float qx[EPB], qy[EPB];
            #pragma unroll
            for (int e = 0; e < EPB; e++) {
                qx[e] = fmaf(tt, vx[e], px[e]);
                qy[e] = fmaf(tt, vy[e], py[e]);
            }
            const long long row = n_est + jp;
            if (full) {
                float4* d = out4 + row * rowF4o + wbase;
                d[0] = make_float4(qx[0], qy[0], s, s);
                d[1] = make_float4(0.f,  qx[1], qy[1], s);
                d[2] = make_float4(s,    0.f,  qx[2], qy[2]);
                d[3] = make_float4(s,    s,    0.f,  qx[3]);
                d[4] = make_float4(qy[3], s,   s,    0.f);
            } else {
                float* d = out + row * B * 5 + (long long)b0 * 5;
                for (int e = 0; e < EPB && b0 + e < B; e++) {
                    d[5*e+0]=qx[e]; d[5*e+1]=qy[e]; d[5*e+2]=s; d[5*e+3]=s; d[5*e+4]=0.f;
                }
            }
        }
    }
}

extern "C" void kernel_launch(void* const* d_in, const int* in_sizes, int n_in,
                              void* d_out, int out_size) {
    const float* inputs  = (const float*)d_in[0];
    const float* sigma_a = (const float*)d_in[1];
    const float* sigma_o = (const float*)d_in[2];
    const float* sigma_i = (const float*)d_in[3];

    const int T_OBS = 10;
    const int B = in_sizes[0] / (T_OBS * 2);
    const int n_est = T_OBS - 1;                // 9
    const int totalSteps = out_size / (B * 5);  // 39
    const int n_pred = totalSteps - n_est;      // 30

    constexpr int BLOCK = 256;
    const int groups = (B + EPB - 1) / EPB;
    dim3 grid((groups + BLOCK - 1) / BLOCK, TCHUNKS);
    kalman_fused_kernel<BLOCK><<<grid, BLOCK>>>(inputs, (float*)d_out,
                                                sigma_a, sigma_o, sigma_i,
                                                B, n_est, n_pred);
}

// round 4
// speedup vs baseline: 1.2339x; 1.2329x over previous
#include <cuda_runtime.h>
#include <math.h>

#define DT 0.1f
#define EPS_STAT 0.01f

template <int BLOCK>
__global__ void __launch_bounds__(BLOCK)
kalman_fused_kernel(const float* __restrict__ in, float* __restrict__ out,
                    const float* __restrict__ sa_p, const float* __restrict__ so_p,
                    const float* __restrict__ si_p,
                    int B, int n_est, int n_pred) {
    // double-buffered (px,py) staging
    __shared__ float buf[2][BLOCK * 2];

    const int tid = threadIdx.x;
    const int blockStart = blockIdx.x * BLOCK;
    const bool fullBlock = (blockStart + BLOCK <= B);
    const int b = min(blockStart + tid, B - 1);

    // ---- uniform covariance constants (computed redundantly per thread) ----
    const float sa = __ldg(sa_p), so = __ldg(so_p), si = __ldg(si_p);
    const float g0  = DT * DT * 0.5f;
    const float q00 = sa * sa * (g0 * g0);
    const float q01 = sa * sa * (g0 * DT);
    const float q11 = sa * sa * (DT * DT);
    const float r   = so * so;
    const float eps2 = EPS_STAT * EPS_STAT;
    float P00 = si * si, P01 = 0.0f, P11 = si * si;

    // ---- init state from rows 0,1 ----
    const float2* __restrict__ zin = reinterpret_cast<const float2*>(in);
    float2 z0 = zin[b];
    float2 z1 = zin[(size_t)B + b];
    float px = z0.x, py = z0.y;
    float vx = (z1.x - z0.x) * (1.0f / DT);
    float vy = (z1.y - z0.y) * (1.0f / DT);
    float2 z = z1;

    const long long rowF4o = (long long)B * 5 / 4;         // float4 per out row
    float4* __restrict__ out4 = reinterpret_cast<float4*>(out);
    const long long outF4base = (long long)blockStart * 5 / 4;
    constexpr int NF4 = BLOCK * 5 / 4;                      // float4 per block-row

    const int total = n_est + n_pred;

    for (int t = 0; t < total; t++) {
        float s_std;
        // ---- covariance predict (uniform) ----
        {
            float nP00 = P00 + 2.0f * DT * P01 + DT * DT * P11 + q00;
            float nP01 = P01 + DT * P11 + q01;
            float nP11 = P11 + q11;
            P00 = nP00; P01 = nP01; P11 = nP11;
        }
        // ---- mean predict ----
        px += DT * vx;
        py += DT * vy;

        if (t < n_est) {
            // gains
            float S  = P00 + r;
            float rs = __frcp_rn(S);
            float K0 = P00 * rs;
            float K1 = P01 * rs;
            // mean update
            float yx = z.x - px, yy = z.y - py;
            px += K0 * yx; vx += K1 * yx;
            py += K0 * yy; vy += K1 * yy;
            // prefetch next measurement
            if (t + 1 < n_est) z = zin[(size_t)(t + 2) * B + b];
            // covariance update (Joseph, uniform)
            float omk = 1.0f - K0;
            float A00 = omk * P00;
            float A01 = omk * P01;
            float A10 = P01 - K1 * P00;
            float A11 = P11 - K1 * P01;
            P00 =  A00 * omk      + r * K0 * K0;
            P01 = -A00 * K1 + A01 + r * K0 * K1;
            P11 = -A10 * K1 + A11 + r * K1 * K1;
        }
        s_std = sqrtf(fmaxf(P00, eps2));

        const int p = t & 1;
        // stage (px,py)
        float2* bp = reinterpret_cast<float2*>(buf[p]);
        bp[tid] = make_float2(px, py);
        __syncthreads();  // orders: all STS(t) done AND all copies(t-1) done

        if (fullBlock) {
            float4* drow = out4 + (long long)t * rowF4o + outF4base;
            #pragma unroll
            for (int f = tid; f < NF4; f += BLOCK) {
                const int cb = f % 5;                    // component block
                const int e0 = 4 * (f / 5);              // first elem of 4-group
                const int e  = e0 + ((cb >= 3) ? 3 : cb); // elem whose pair we need
                const float2 pr = bp[e];
                float4 v;
                switch (cb) {
                    case 0: v = make_float4(pr.x, pr.y, s_std, s_std); break;
                    case 1: v = make_float4(0.f,  pr.x, pr.y, s_std);  break;
                    case 2: v = make_float4(s_std, 0.f,  pr.x, pr.y);  break;
                    case 3: v = make_float4(s_std, s_std, 0.f,  pr.x); break;
                    default:v = make_float4(pr.y, s_std, s_std, 0.f);  break;
                }
                drow[f] = v;
            }
        } else {
            // tail block: scalar stores for valid elems only
            if (blockStart + tid < B) {
                float* d = out + (long long)t * B * 5 + (long long)(blockStart + tid) * 5;
                d[0] = px; d[1] = py; d[2] = s_std; d[3] = s_std; d[4] = 0.f;
            }
        }
        // no second barrier: next iteration writes buf[(t+1)&1], whose readers
        // (copy of step t-1) completed before this iteration's __syncthreads.
    }
}

extern "C" void kernel_launch(void* const* d_in, const int* in_sizes, int n_in,
                              void* d_out, int out_size) {
    const float* inputs  = (const float*)d_in[0];
    const float* sigma_a = (const float*)d_in[1];
    const float* sigma_o = (const float*)d_in[2];
    const float* sigma_i = (const float*)d_in[3];

    const int T_OBS = 10;
    const int B = in_sizes[0] / (T_OBS * 2);
    const int n_est = T_OBS - 1;                // 9
    const int totalSteps = out_size / (B * 5);  // 39
    const int n_pred = totalSteps - n_est;      // 30

    constexpr int BLOCK = 256;
    const int grid = (B + BLOCK - 1) / BLOCK;
    kalman_fused_kernel<BLOCK><<<grid, BLOCK>>>(inputs, (float*)d_out,
                                                sigma_a, sigma_o, sigma_i,
                                                B, n_est, n_pred);
}

// round 5
// speedup vs baseline: 1.5136x; 1.2267x over previous
#include <cuda_runtime.h>
#include <math.h>

#define DT 0.1f
#define EPS_STAT 0.01f

template <int BLOCK>
__global__ void __launch_bounds__(BLOCK)
kalman_kernel(const float* __restrict__ in, float* __restrict__ out,
              const float* __restrict__ sa_p, const float* __restrict__ so_p,
              const float* __restrict__ si_p,
              int B, int n_est, int n_pred) {
    // uniform per-step tables
    __shared__ float4 gt[16];   // est steps: (K0, K1, s, 0)
    __shared__ float  st[64];   // pred steps: s
    // double-buffered full-row staging: [px,py,s,s,0] per element
    __shared__ float  buf[2][BLOCK * 5];

    const int tid = threadIdx.x;
    const int blockStart = blockIdx.x * BLOCK;
    const bool fullBlock = (blockStart + BLOCK <= B);
    const int b = min(blockStart + tid, B - 1);
    const int total = n_est + n_pred;

    // ---- thread 0: uniform covariance recursion -> gain/std tables ----
    if (tid == 0) {
        const float sa = *sa_p, so = *so_p, si = *si_p;
        const float g0  = DT * DT * 0.5f;
        const float q00 = sa * sa * (g0 * g0);
        const float q01 = sa * sa * (g0 * DT);
        const float q11 = sa * sa * (DT * DT);
        const float r   = so * so;
        const float eps2 = EPS_STAT * EPS_STAT;
        float P00 = si * si, P01 = 0.0f, P11 = si * si;
        for (int k = 0; k < n_est; k++) {
            float a = P00 + 2.0f * DT * P01 + DT * DT * P11 + q00;
            float c = P01 + DT * P11 + q01;
            float d = P11 + q11;
            P00 = a; P01 = c; P11 = d;
            float S = P00 + r, rs = 1.0f / S;
            float K0 = P00 * rs, K1 = P01 * rs;
            float omk = 1.0f - K0;
            float A00 = omk * P00;
            float A01 = omk * P01;
            float A10 = P01 - K1 * P00;
            float A11 = P11 - K1 * P01;
            P00 =  A00 * omk      + r * K0 * K0;
            P01 = -A00 * K1 + A01 + r * K0 * K1;
            P11 = -A10 * K1 + A11 + r * K1 * K1;
            gt[k] = make_float4(K0, K1, sqrtf(fmaxf(P00, eps2)), 0.0f);
        }
        for (int j = 0; j < n_pred; j++) {
            float a = P00 + 2.0f * DT * P01 + DT * DT * P11 + q00;
            float c = P01 + DT * P11 + q01;
            float d = P11 + q11;
            P00 = a; P01 = c; P11 = d;
            st[j] = sqrtf(fmaxf(P00, eps2));
        }
    }

    // ---- init state from rows 0,1 ----
    const float2* __restrict__ zin = reinterpret_cast<const float2*>(in);
    float2 z0 = zin[b];
    float2 z1 = zin[(size_t)B + b];
    float px = z0.x, py = z0.y;
    float vx = (z1.x - z0.x) * (1.0f / DT);
    float vy = (z1.y - z0.y) * (1.0f / DT);
    float2 z = z1;

    // constant zero slots (never touched again)
    buf[0][tid * 5 + 4] = 0.0f;
    buf[1][tid * 5 + 4] = 0.0f;
    __syncthreads();  // tables + zeros visible

    // precomputed copy-out indexing (constant across steps)
    constexpr int NF4 = BLOCK * 5 / 4;
    const long long rowF4o = (long long)B * 5 / 4;
    float4* __restrict__ drow =
        reinterpret_cast<float4*>(out) + (long long)blockStart * 5 / 4;
    float* __restrict__ myrow0 = &buf[0][tid * 5];
    float* __restrict__ myrow1 = &buf[1][tid * 5];
    const bool extra = (tid < NF4 - BLOCK);

    for (int t = 0; t < total; t++) {
        float s;
        // mean predict
        px += DT * vx;
        py += DT * vy;

        if (t < n_est) {
            float4 g = gt[t];                 // broadcast LDS.128
            float yx = z.x - px, yy = z.y - py;
            px += g.x * yx; vx += g.y * yx;
            py += g.x * yy; vy += g.y * yy;
            if (t + 1 < n_est) z = zin[(size_t)(t + 2) * B + b];
            s = g.z;
        } else {
            s = st[t - n_est];                // broadcast LDS.32
        }

        // stage row (the trailing 0 is pre-written)
        float* row = (t & 1) ? myrow1 : myrow0;
        row[0] = px; row[1] = py; row[2] = s; row[3] = s;
        __syncthreads();  // orders STS(t) and copies(t-1)

        if (fullBlock) {
            const float4* sbuf =
                reinterpret_cast<const float4*>(buf[t & 1]);
            drow[tid] = sbuf[tid];
            if (extra) drow[tid + BLOCK] = sbuf[tid + BLOCK];
        } else if (blockStart + tid < B) {
            float* d = out + (long long)t * B * 5 + (long long)(blockStart + tid) * 5;
            d[0] = px; d[1] = py; d[2] = s; d[3] = s; d[4] = 0.0f;
        }
        drow += rowF4o;
        // next step writes the other buffer; copies of this step complete
        // before the next __syncthreads -> no second barrier needed.
    }
}

extern "C" void kernel_launch(void* const* d_in, const int* in_sizes, int n_in,
                              void* d_out, int out_size) {
    const float* inputs  = (const float*)d_in[0];
    const float* sigma_a = (const float*)d_in[1];
    const float* sigma_o = (const float*)d_in[2];
    const float* sigma_i = (const float*)d_in[3];

    const int T_OBS = 10;
    const int B = in_sizes[0] / (T_OBS * 2);
    const int n_est = T_OBS - 1;                // 9
    const int totalSteps = out_size / (B * 5);  // 39
    const int n_pred = totalSteps - n_est;      // 30

    constexpr int BLOCK = 256;
    const int grid = (B + BLOCK - 1) / BLOCK;
    kalman_kernel<BLOCK><<<grid, BLOCK>>>(inputs, (float*)d_out,
                                          sigma_a, sigma_o, sigma_i,
                                          B, n_est, n_pred);
}